// round 6
// baseline (speedup 1.0000x reference)
#include <cuda_runtime.h>
#include <cuda_bf16.h>
#include <cstdint>

// Problem constants (fixed by reference):
//   g: (32, 16, 2048, 3) fp32, ar_phi: (3,3), ar_eta: (3,), ar_c: (3,)
//   P=3, KMAX=5 (11 windings), output: (32,) fp32
#define N_MC      32
#define N_SAMP    16
#define N_ROWS    (N_MC * N_SAMP)       // 512
#define T_LEN     2048
#define TPRIME    2044                   // T - 1 - P
#define ROW_ELEMS (T_LEN * 3)            // 6144 floats
#define ROW_VEC4  (ROW_ELEMS / 4)        // 1536 float4s per row

#define BLOCK     256
#define CHUNK     8                      // t-outputs per thread

#define PI_F      3.14159265358979323846f
#define TWO_PI_F  6.28318530717958647693f
#define INV_2PI_F 0.15915494309189533577f

// Fixed-point scale for deterministic integer accumulation. One rounding per
// block per dim (16 per output) at 2^-30 -> total error ~1.5e-8 absolute,
// vs tolerance budget ~8.5e7. Max sum per row*dim < 4e4 -> q < 4.3e13;
// 16 blocks -> < 7e14, far below 2^63 and below 2^53 (exact as double).
#define FXSCALE   1073741824.0f          // 2^30
#define INV_FX    (1.0 / 1073741824.0)

// Deterministic scratch: integer sums + per-m tickets. Zero at module load;
// the finalizing block resets its m's entries each launch -> replay-safe.
__device__ unsigned long long g_sum[N_MC][3];
__device__ unsigned int g_tick[N_MC];

// Torus logmap, cheap form: x - 2*pi*rint(x/2pi). Matches mod(x+pi,2pi)-pi
// except at exact half-period boundaries (measure zero in fp32 data).
__device__ __forceinline__ float wrapf(float x) {
    return fmaf(-rintf(x * INV_2PI_F), TWO_PI_F, x);
}

__global__ __launch_bounds__(BLOCK)
void arp_flat_kernel(const float* __restrict__ g,
                     const float* __restrict__ ar_phi,
                     const float* __restrict__ ar_eta,
                     const float* __restrict__ ar_c,
                     float* __restrict__ out) {
    __shared__ float sred[3][BLOCK / 32];

    const int tid = threadIdx.x;
    const int row = blockIdx.x;          // (m*16 + s)
    const int m   = row >> 4;

    // Small params (L1-cached broadcast loads).
    float ph[3][3], cc[3];
#pragma unroll
    for (int d = 0; d < 3; d++) {
        ph[d][0] = __ldg(&ar_phi[d * 3 + 0]);
        ph[d][1] = __ldg(&ar_phi[d * 3 + 1]);
        ph[d][2] = __ldg(&ar_phi[d * 3 + 2]);
        cc[d]    = __ldg(&ar_c[d]);
    }

    // ---- Direct vectorized load: angles t0..t0+11, all 3 dims = 36 floats
    // = 9 consecutive float4s (3*t0 divisible by 4 since t0 % 8 == 0).
    const int t0   = tid * CHUNK;
    const int base = (3 * t0) >> 2;
    const float4* g4 = reinterpret_cast<const float4*>(g)
                     + (size_t)row * ROW_VEC4;
    float f[36];
#pragma unroll
    for (int k = 0; k < 9; k++) {
        int idx = base + k;
        if (idx > ROW_VEC4 - 1) idx = ROW_VEC4 - 1;   // tail clamp (unused data)
        float4 v = __ldg(&g4[idx]);
        f[4 * k + 0] = v.x; f[4 * k + 1] = v.y;
        f[4 * k + 2] = v.z; f[4 * k + 3] = v.w;
    }

    // ---- AR(3) on wrapped first-diffs; each dx computed exactly once.
    float acc[3];
#pragma unroll
    for (int d = 0; d < 3; d++) {
        float dx[CHUNK + 3];
#pragma unroll
        for (int j = 0; j < CHUNK + 3; j++)
            dx[j] = wrapf(f[3 * (j + 1) + d] - f[3 * j + d]);
        float ss = 0.f;
#pragma unroll
        for (int j = 0; j < CHUNK; j++) {
            float dyv = dx[j + 3] - (ph[d][0] * dx[j + 2]
                                   + ph[d][1] * dx[j + 1]
                                   + ph[d][2] * dx[j]);
            float u = dyv - cc[d];
            if (t0 + j < TPRIME) ss = fmaf(u, u, ss);
        }
        acc[d] = ss;
    }

    // ---- Warp reduce, then 8-warp fold.
#pragma unroll
    for (int off = 16; off; off >>= 1)
#pragma unroll
        for (int d = 0; d < 3; d++)
            acc[d] += __shfl_xor_sync(0xffffffffu, acc[d], off);

    const int lane = tid & 31;
    const int warp = tid >> 5;
    if (lane == 0)
#pragma unroll
        for (int d = 0; d < 3; d++) sred[d][warp] = acc[d];
    __syncthreads();

    // ---- tid0: deterministic integer accumulation + per-m completion ticket.
    if (tid == 0) {
#pragma unroll
        for (int d = 0; d < 3; d++) {
            float S = sred[d][0];
#pragma unroll
            for (int w = 1; w < BLOCK / 32; w++) S += sred[d][w];
            unsigned long long q =
                (unsigned long long)__float2ll_rn(S * FXSCALE);
            atomicAdd(&g_sum[m][d], q);   // integer add: order-independent
        }
        __threadfence();                   // release sums before ticket
        unsigned int t = atomicAdd(&g_tick[m], 1u);

        // Last-arriving block for this m finalizes out[m] immediately.
        if (t == N_SAMP - 1) {
            __threadfence();               // acquire other blocks' sums
            float res = 0.f;
#pragma unroll
            for (int d = 0; d < 3; d++) {
                unsigned long long q2 =
                    *(volatile unsigned long long*)&g_sum[m][d];
                float Sd = (float)((double)q2 * INV_FX);
                float e   = fabsf(__ldg(&ar_eta[d]));   // scale = sqrt(eta^2)
                float var = e * e;
                // sum_{k=-5..5} winding log-density collapses
                // (sum k = 0, sum k^2 = 110) per (t,d) to:
                //   -5.5*u^2/var - 220*pi^2/var - 11*log(e) - 5.5*log(2*pi)
                float C = -220.f * (PI_F * PI_F) / var - 11.f * logf(e)
                          - 5.5f * logf(TWO_PI_F);
                res += -5.5f * Sd / var + (float)(N_SAMP * TPRIME) * C;
            }
            out[m] = res;
            // Reset this m's scratch for the next graph replay.
#pragma unroll
            for (int d = 0; d < 3; d++)
                *(volatile unsigned long long*)&g_sum[m][d] = 0ull;
            *(volatile unsigned int*)&g_tick[m] = 0u;
        }
    }
}

extern "C" void kernel_launch(void* const* d_in, const int* in_sizes, int n_in,
                              void* d_out, int out_size) {
    const float* g      = (const float*)d_in[0];
    const float* ar_phi = (const float*)d_in[1];
    const float* ar_eta = (const float*)d_in[2];
    const float* ar_c   = (const float*)d_in[3];
    float* out = (float*)d_out;

    arp_flat_kernel<<<N_ROWS, BLOCK>>>(g, ar_phi, ar_eta, ar_c, out);
}